// round 1
// baseline (speedup 1.0000x reference)
#include <cuda_runtime.h>
#include <math.h>

#define CC 8
#define HH 256
#define WW 256
#define BB 8
#define NB 4
#define TX 32
#define TY 8
#define NT (TX*TY)

// scratch (no allocations allowed): f features + d1 ping-pong
__device__ float g_f[(size_t)BB*CC*HH*WW];
__device__ float g_d1[2][(size_t)BB*CC*HH*WW];

// ---------------------------------------------------------------------------
// Stage A: f = conv(d1, We); w1 = paconv(f, Wp) * f; x1 = softargmax(d1, w1)
// writes f (core) to g_f and x1 to out[b, blk, :, :]
// ---------------------------------------------------------------------------
__global__ __launch_bounds__(NT) void k_stage_a(
    const float* __restrict__ d1_ext, int src,
    const float* __restrict__ We, const float* __restrict__ Wp,
    float* __restrict__ out, int blk)
{
    __shared__ float s_d1[CC][TY+4][TX+4];   // halo 2
    __shared__ float s_f [CC][TY+2][TX+2];   // halo 1
    __shared__ float s_We[CC*CC*9];
    __shared__ float s_Wp[CC*CC*9];

    const int tid = threadIdx.x;
    const int b  = blockIdx.z;
    const int x0 = blockIdx.x * TX;
    const int y0 = blockIdx.y * TY;

    const float* d1p = d1_ext ? d1_ext : &g_d1[src][0];
    const float* d1b = d1p + (size_t)b * CC * HH * WW;

    for (int i = tid; i < CC*CC*9; i += NT) { s_We[i] = We[i]; s_Wp[i] = Wp[i]; }

    // load d1 tile with halo 2 (zero pad)
    for (int i = tid; i < CC*(TY+4)*(TX+4); i += NT) {
        int c  = i / ((TY+4)*(TX+4));
        int r  = i % ((TY+4)*(TX+4));
        int ly = r / (TX+4), lx = r % (TX+4);
        int gy = y0 + ly - 2, gx = x0 + lx - 2;
        float v = 0.f;
        if (gy >= 0 && gy < HH && gx >= 0 && gx < WW)
            v = d1b[((size_t)c*HH + gy)*WW + gx];
        s_d1[c][ly][lx] = v;
    }
    __syncthreads();

    // compute f on halo-1 extended tile (zero outside image: patches() zero-pads f)
    for (int i = tid; i < (TY+2)*(TX+2); i += NT) {
        int ly = i / (TX+2), lx = i % (TX+2);
        int gy = y0 + ly - 1, gx = x0 + lx - 1;
        float acc[CC];
        #pragma unroll
        for (int o = 0; o < CC; o++) acc[o] = 0.f;
        if (gy >= 0 && gy < HH && gx >= 0 && gx < WW) {
            #pragma unroll
            for (int c = 0; c < CC; c++) {
                #pragma unroll
                for (int k = 0; k < 9; k++) {
                    float v = s_d1[c][ly + k/3][lx + k%3];
                    #pragma unroll
                    for (int o = 0; o < CC; o++)
                        acc[o] = fmaf(v, s_We[o*72 + c*9 + k], acc[o]);
                }
            }
        }
        #pragma unroll
        for (int o = 0; o < CC; o++) s_f[o][ly][lx] = acc[o];
    }
    __syncthreads();

    // per-thread core pixel
    const int ty = tid / TX, tx = tid % TX;
    float fc[CC];
    #pragma unroll
    for (int c = 0; c < CC; c++) fc[c] = s_f[c][ty+1][tx+1];

    float acc[CC];
    #pragma unroll
    for (int o = 0; o < CC; o++) acc[o] = 0.f;

    #pragma unroll
    for (int k = 0; k < 9; k++) {
        const int dy = k/3, dx = k%3;
        float s = 0.f;
        #pragma unroll
        for (int c = 0; c < CC; c++) {
            float d = s_f[c][ty+dy][tx+dx] - fc[c];
            s = fmaf(d, d, s);
        }
        float kern = __expf(-0.5f * s);
        #pragma unroll
        for (int c = 0; c < CC; c++) {
            float v = s_f[c][ty+dy][tx+dx] * kern;
            #pragma unroll
            for (int o = 0; o < CC; o++)
                acc[o] = fmaf(v, s_Wp[o*72 + c*9 + k], acc[o]);
        }
    }

    // w1 = paconv * f ; softargmax over channels with tau=10
    float w1[CC];
    float m = -1e30f;
    #pragma unroll
    for (int c = 0; c < CC; c++) {
        w1[c] = acc[c] * fc[c] * 10.0f;
        m = fmaxf(m, w1[c]);
    }
    float se = 0.f, sd = 0.f;
    #pragma unroll
    for (int c = 0; c < CC; c++) {
        float e = __expf(w1[c] - m);
        se += e;
        sd = fmaf(e, s_d1[c][ty+2][tx+2], sd);
    }
    float x1 = sd / se;

    const int gy = y0 + ty, gx = x0 + tx;
    out[(((size_t)b*NB + blk)*HH + gy)*WW + gx] = x1;
    float* fo = g_f + (size_t)b * CC * HH * WW;
    #pragma unroll
    for (int c = 0; c < CC; c++)
        fo[((size_t)c*HH + gy)*WW + gx] = fc[c];
}

// ---------------------------------------------------------------------------
// Stage B: fx = conv(|d1-x1|, We2); ws = paconv_group([f,fx] interleave)*ALPHA;
// d1_new = d1 + sigmoid(ALPHA*(ws1-ws0)) * (x1 - d1)
// ---------------------------------------------------------------------------
__global__ __launch_bounds__(NT) void k_stage_b(
    const float* __restrict__ d1_ext, int src, int dst,
    const float* __restrict__ x1base,  // out + blk*H*W, batch stride NB*H*W
    const float* __restrict__ We2, const float* __restrict__ Wg)
{
    __shared__ float s_d1[CC][TY+4][TX+4];
    __shared__ float s_x1[TY+4][TX+4];
    __shared__ float s_f [CC][TY+2][TX+2];
    __shared__ float s_fx[CC][TY+2][TX+2];
    __shared__ float s_We2[CC*CC*9];
    __shared__ float s_Wg[CC*2*2*9];

    const int tid = threadIdx.x;
    const int b  = blockIdx.z;
    const int x0 = blockIdx.x * TX;
    const int y0 = blockIdx.y * TY;

    const float* d1p = d1_ext ? d1_ext : &g_d1[src][0];
    const float* d1b = d1p + (size_t)b * CC * HH * WW;
    const float* x1b = x1base + (size_t)b * NB * HH * WW;
    const float* fb  = g_f + (size_t)b * CC * HH * WW;

    for (int i = tid; i < CC*CC*9; i += NT) s_We2[i] = We2[i];
    for (int i = tid; i < CC*2*2*9; i += NT) s_Wg[i] = Wg[i];

    // d1 halo-2
    for (int i = tid; i < CC*(TY+4)*(TX+4); i += NT) {
        int c  = i / ((TY+4)*(TX+4));
        int r  = i % ((TY+4)*(TX+4));
        int ly = r / (TX+4), lx = r % (TX+4);
        int gy = y0 + ly - 2, gx = x0 + lx - 2;
        float v = 0.f;
        if (gy >= 0 && gy < HH && gx >= 0 && gx < WW)
            v = d1b[((size_t)c*HH + gy)*WW + gx];
        s_d1[c][ly][lx] = v;
    }
    // x1 halo-2
    for (int i = tid; i < (TY+4)*(TX+4); i += NT) {
        int ly = i / (TX+4), lx = i % (TX+4);
        int gy = y0 + ly - 2, gx = x0 + lx - 2;
        float v = 0.f;
        if (gy >= 0 && gy < HH && gx >= 0 && gx < WW)
            v = x1b[(size_t)gy*WW + gx];
        s_x1[ly][lx] = v;
    }
    // f halo-1 (zero outside image -> matches patches() zero pad)
    for (int i = tid; i < CC*(TY+2)*(TX+2); i += NT) {
        int c  = i / ((TY+2)*(TX+2));
        int r  = i % ((TY+2)*(TX+2));
        int ly = r / (TX+2), lx = r % (TX+2);
        int gy = y0 + ly - 1, gx = x0 + lx - 1;
        float v = 0.f;
        if (gy >= 0 && gy < HH && gx >= 0 && gx < WW)
            v = fb[((size_t)c*HH + gy)*WW + gx];
        s_f[c][ly][lx] = v;
    }
    __syncthreads();

    // fx on halo-1 extended tile, conv of d_x = |d1 - x1| (zero outside image)
    for (int i = tid; i < (TY+2)*(TX+2); i += NT) {
        int ly = i / (TX+2), lx = i % (TX+2);
        int gy = y0 + ly - 1, gx = x0 + lx - 1;
        float acc[CC];
        #pragma unroll
        for (int o = 0; o < CC; o++) acc[o] = 0.f;
        if (gy >= 0 && gy < HH && gx >= 0 && gx < WW) {
            #pragma unroll
            for (int c = 0; c < CC; c++) {
                #pragma unroll
                for (int k = 0; k < 9; k++) {
                    int yy = ly + k/3, xx = lx + k%3;
                    float v = fabsf(s_d1[c][yy][xx] - s_x1[yy][xx]);
                    #pragma unroll
                    for (int o = 0; o < CC; o++)
                        acc[o] = fmaf(v, s_We2[o*72 + c*9 + k], acc[o]);
                }
            }
        }
        #pragma unroll
        for (int o = 0; o < CC; o++) s_fx[o][ly][lx] = acc[o];
    }
    __syncthreads();

    const int ty = tid / TX, tx = tid % TX;
    const int gy = y0 + ty, gx = x0 + tx;
    const float x1c = s_x1[ty+2][tx+2];
    float* dout = &g_d1[dst][0] + (size_t)b * CC * HH * WW;

    #pragma unroll
    for (int g = 0; g < CC; g++) {
        const float cf  = s_f [g][ty+1][tx+1];
        const float cfx = s_fx[g][ty+1][tx+1];
        float ws0 = 0.f, ws1 = 0.f;
        #pragma unroll
        for (int k = 0; k < 9; k++) {
            const int dy = k/3, dx = k%3;
            float pf  = s_f [g][ty+dy][tx+dx];
            float pfx = s_fx[g][ty+dy][tx+dx];
            float df = pf - cf, dfx = pfx - cfx;
            float kern = __expf(-0.5f * fmaf(df, df, dfx*dfx));
            // wg[g][o][cin][k] at (g*2+o)*18 + cin*9 + k
            ws0 = fmaf(kern, fmaf(pf, s_Wg[(g*2+0)*18 + k], pfx * s_Wg[(g*2+0)*18 + 9 + k]), ws0);
            ws1 = fmaf(kern, fmaf(pf, s_Wg[(g*2+1)*18 + k], pfx * s_Wg[(g*2+1)*18 + 9 + k]), ws1);
        }
        // softmax over (ALPHA*ws0, ALPHA*ws1), blend pairs (d1, x1)
        float s = 1.f / (1.f + __expf(-2.0f * (ws1 - ws0)));
        float d1c = s_d1[g][ty+2][tx+2];
        dout[((size_t)g*HH + gy)*WW + gx] = d1c + s * (x1c - d1c);
    }
}

// ---------------------------------------------------------------------------
extern "C" void kernel_launch(void* const* d_in, const int* in_sizes, int n_in,
                              void* d_out, int out_size)
{
    const float* d1  = (const float*)d_in[0];
    const float* We  = (const float*)d_in[1];
    const float* Wp  = (const float*)d_in[2];
    const float* We2 = (const float*)d_in[3];
    const float* Wg  = (const float*)d_in[4];
    float* out = (float*)d_out;

    dim3 grid(WW/TX, HH/TY, BB);
    const int HW = HH * WW;
    const int WSZ = CC*CC*9;     // 576 per block for We/Wp/We2
    const int GSZ = CC*2*9*2;    // 288 per block for Wg

    // block 0 reads the external input d1
    k_stage_a<<<grid, NT>>>(d1, 0, We + 0*WSZ, Wp + 0*WSZ, out, 0);
    k_stage_b<<<grid, NT>>>(d1, 0, 0, out + 0*HW, We2 + 0*WSZ, Wg + 0*GSZ);

    k_stage_a<<<grid, NT>>>(nullptr, 0, We + 1*WSZ, Wp + 1*WSZ, out, 1);
    k_stage_b<<<grid, NT>>>(nullptr, 0, 1, out + 1*HW, We2 + 1*WSZ, Wg + 1*GSZ);

    k_stage_a<<<grid, NT>>>(nullptr, 1, We + 2*WSZ, Wp + 2*WSZ, out, 2);
    k_stage_b<<<grid, NT>>>(nullptr, 1, 0, out + 2*HW, We2 + 2*WSZ, Wg + 2*GSZ);

    k_stage_a<<<grid, NT>>>(nullptr, 0, We + 3*WSZ, Wp + 3*WSZ, out, 3);
}

// round 2
// speedup vs baseline: 1.5501x; 1.5501x over previous
#include <cuda_runtime.h>
#include <math.h>

#define CC 8
#define HH 256
#define WW 256
#define BB 8
#define NB 4
#define TX 32
#define TY 8
#define NT (TX*TY)

// scratch (no allocations allowed): f features + d1 ping-pong
__device__ float g_f[(size_t)BB*CC*HH*WW];
__device__ float g_d1[2][(size_t)BB*CC*HH*WW];

// ---------------------------------------------------------------------------
// Stage A: f = conv(d1, We); w1 = paconv(f, Wp) * f; x1 = softargmax(d1, w1)
// weights staged in smem transposed to [cin][k][o] so the o-loop is 2x LDS.128
// ---------------------------------------------------------------------------
__global__ __launch_bounds__(NT, 2) void k_stage_a(
    const float* __restrict__ d1_ext, int src,
    const float* __restrict__ We, const float* __restrict__ Wp,
    float* __restrict__ out, int blk)
{
    __shared__ float s_d1[CC][TY+4][TX+4];   // halo 2
    __shared__ float s_f [CC][TY+2][TX+2];   // halo 1
    __shared__ __align__(16) float s_We[CC*9*CC];   // [c][k][o]
    __shared__ __align__(16) float s_Wp[CC*9*CC];   // [c][k][o]

    const int tid = threadIdx.x;
    const int b  = blockIdx.z;
    const int x0 = blockIdx.x * TX;
    const int y0 = blockIdx.y * TY;

    const float* d1p = d1_ext ? d1_ext : &g_d1[src][0];
    const float* d1b = d1p + (size_t)b * CC * HH * WW;

    // load weights transposed: src [o][c][k] -> dst [c][k][o]
    for (int i = tid; i < CC*CC*9; i += NT) {
        int o = i / 72, r = i % 72, c = r / 9, k = r % 9;
        s_We[c*72 + k*8 + o] = We[i];
        s_Wp[c*72 + k*8 + o] = Wp[i];
    }

    // load d1 tile with halo 2 (zero pad)
    for (int i = tid; i < CC*(TY+4)*(TX+4); i += NT) {
        int c  = i / ((TY+4)*(TX+4));
        int r  = i % ((TY+4)*(TX+4));
        int ly = r / (TX+4), lx = r % (TX+4);
        int gy = y0 + ly - 2, gx = x0 + lx - 2;
        float v = 0.f;
        if (gy >= 0 && gy < HH && gx >= 0 && gx < WW)
            v = d1b[((size_t)c*HH + gy)*WW + gx];
        s_d1[c][ly][lx] = v;
    }
    __syncthreads();

    // compute f on halo-1 extended tile (zero outside image)
    for (int i = tid; i < (TY+2)*(TX+2); i += NT) {
        int ly = i / (TX+2), lx = i % (TX+2);
        int gy = y0 + ly - 1, gx = x0 + lx - 1;
        float a0 = 0.f, a1 = 0.f, a2 = 0.f, a3 = 0.f;
        float a4 = 0.f, a5 = 0.f, a6 = 0.f, a7 = 0.f;
        if (gy >= 0 && gy < HH && gx >= 0 && gx < WW) {
            #pragma unroll
            for (int c = 0; c < CC; c++) {
                #pragma unroll
                for (int k = 0; k < 9; k++) {
                    float v = s_d1[c][ly + k/3][lx + k%3];
                    float4 wa = *(const float4*)&s_We[c*72 + k*8];
                    float4 wb = *(const float4*)&s_We[c*72 + k*8 + 4];
                    a0 = fmaf(v, wa.x, a0); a1 = fmaf(v, wa.y, a1);
                    a2 = fmaf(v, wa.z, a2); a3 = fmaf(v, wa.w, a3);
                    a4 = fmaf(v, wb.x, a4); a5 = fmaf(v, wb.y, a5);
                    a6 = fmaf(v, wb.z, a6); a7 = fmaf(v, wb.w, a7);
                }
            }
        }
        s_f[0][ly][lx] = a0; s_f[1][ly][lx] = a1;
        s_f[2][ly][lx] = a2; s_f[3][ly][lx] = a3;
        s_f[4][ly][lx] = a4; s_f[5][ly][lx] = a5;
        s_f[6][ly][lx] = a6; s_f[7][ly][lx] = a7;
    }
    __syncthreads();

    // per-thread core pixel
    const int ty = tid / TX, tx = tid % TX;
    float fc[CC];
    #pragma unroll
    for (int c = 0; c < CC; c++) fc[c] = s_f[c][ty+1][tx+1];

    float a0 = 0.f, a1 = 0.f, a2 = 0.f, a3 = 0.f;
    float a4 = 0.f, a5 = 0.f, a6 = 0.f, a7 = 0.f;

    #pragma unroll
    for (int k = 0; k < 9; k++) {
        const int dy = k/3, dx = k%3;
        float s = 0.f;
        float pv[CC];
        #pragma unroll
        for (int c = 0; c < CC; c++) {
            pv[c] = s_f[c][ty+dy][tx+dx];
            float d = pv[c] - fc[c];
            s = fmaf(d, d, s);
        }
        float kern = __expf(-0.5f * s);
        #pragma unroll
        for (int c = 0; c < CC; c++) {
            float v = pv[c] * kern;
            float4 wa = *(const float4*)&s_Wp[c*72 + k*8];
            float4 wb = *(const float4*)&s_Wp[c*72 + k*8 + 4];
            a0 = fmaf(v, wa.x, a0); a1 = fmaf(v, wa.y, a1);
            a2 = fmaf(v, wa.z, a2); a3 = fmaf(v, wa.w, a3);
            a4 = fmaf(v, wb.x, a4); a5 = fmaf(v, wb.y, a5);
            a6 = fmaf(v, wb.z, a6); a7 = fmaf(v, wb.w, a7);
        }
    }

    // w1 = paconv * f ; softargmax over channels with tau=10
    float w1[CC];
    w1[0] = a0*fc[0]*10.f; w1[1] = a1*fc[1]*10.f;
    w1[2] = a2*fc[2]*10.f; w1[3] = a3*fc[3]*10.f;
    w1[4] = a4*fc[4]*10.f; w1[5] = a5*fc[5]*10.f;
    w1[6] = a6*fc[6]*10.f; w1[7] = a7*fc[7]*10.f;
    float m = -1e30f;
    #pragma unroll
    for (int c = 0; c < CC; c++) m = fmaxf(m, w1[c]);
    float se = 0.f, sd = 0.f;
    #pragma unroll
    for (int c = 0; c < CC; c++) {
        float e = __expf(w1[c] - m);
        se += e;
        sd = fmaf(e, s_d1[c][ty+2][tx+2], sd);
    }
    float x1 = sd / se;

    const int gy = y0 + ty, gx = x0 + tx;
    out[(((size_t)b*NB + blk)*HH + gy)*WW + gx] = x1;
    float* fo = g_f + (size_t)b * CC * HH * WW;
    #pragma unroll
    for (int c = 0; c < CC; c++)
        fo[((size_t)c*HH + gy)*WW + gx] = fc[c];
}

// ---------------------------------------------------------------------------
// Stage B: fx = conv(|d1-x1|, We2); ws = paconv_group([f,fx])*ALPHA;
// d1_new = d1 + sigmoid(ALPHA*(ws1-ws0)) * (x1 - d1)
// ---------------------------------------------------------------------------
__global__ __launch_bounds__(NT, 2) void k_stage_b(
    const float* __restrict__ d1_ext, int src, int dst,
    const float* __restrict__ x1base,  // out + blk*H*W, batch stride NB*H*W
    const float* __restrict__ We2, const float* __restrict__ Wg)
{
    __shared__ float s_d1[CC][TY+4][TX+4];
    __shared__ float s_x1[TY+4][TX+4];
    __shared__ float s_f [CC][TY+2][TX+2];
    __shared__ float s_fx[CC][TY+2][TX+2];
    __shared__ __align__(16) float s_We2[CC*9*CC];   // [c][k][o]
    __shared__ __align__(16) float4 s_Wg4[CC*9];     // (w00,w01,w10,w11) per (g,k)

    const int tid = threadIdx.x;
    const int b  = blockIdx.z;
    const int x0 = blockIdx.x * TX;
    const int y0 = blockIdx.y * TY;

    const float* d1p = d1_ext ? d1_ext : &g_d1[src][0];
    const float* d1b = d1p + (size_t)b * CC * HH * WW;
    const float* x1b = x1base + (size_t)b * NB * HH * WW;
    const float* fb  = g_f + (size_t)b * CC * HH * WW;

    for (int i = tid; i < CC*CC*9; i += NT) {
        int o = i / 72, r = i % 72, c = r / 9, k = r % 9;
        s_We2[c*72 + k*8 + o] = We2[i];
    }
    for (int i = tid; i < CC*9; i += NT) {
        int g = i / 9, k = i % 9;
        s_Wg4[i] = make_float4(Wg[(g*2+0)*18 + k], Wg[(g*2+0)*18 + 9 + k],
                               Wg[(g*2+1)*18 + k], Wg[(g*2+1)*18 + 9 + k]);
    }

    // d1 halo-2
    for (int i = tid; i < CC*(TY+4)*(TX+4); i += NT) {
        int c  = i / ((TY+4)*(TX+4));
        int r  = i % ((TY+4)*(TX+4));
        int ly = r / (TX+4), lx = r % (TX+4);
        int gy = y0 + ly - 2, gx = x0 + lx - 2;
        float v = 0.f;
        if (gy >= 0 && gy < HH && gx >= 0 && gx < WW)
            v = d1b[((size_t)c*HH + gy)*WW + gx];
        s_d1[c][ly][lx] = v;
    }
    // x1 halo-2
    for (int i = tid; i < (TY+4)*(TX+4); i += NT) {
        int ly = i / (TX+4), lx = i % (TX+4);
        int gy = y0 + ly - 2, gx = x0 + lx - 2;
        float v = 0.f;
        if (gy >= 0 && gy < HH && gx >= 0 && gx < WW)
            v = x1b[(size_t)gy*WW + gx];
        s_x1[ly][lx] = v;
    }
    // f halo-1 (zero outside image)
    for (int i = tid; i < CC*(TY+2)*(TX+2); i += NT) {
        int c  = i / ((TY+2)*(TX+2));
        int r  = i % ((TY+2)*(TX+2));
        int ly = r / (TX+2), lx = r % (TX+2);
        int gy = y0 + ly - 1, gx = x0 + lx - 1;
        float v = 0.f;
        if (gy >= 0 && gy < HH && gx >= 0 && gx < WW)
            v = fb[((size_t)c*HH + gy)*WW + gx];
        s_f[c][ly][lx] = v;
    }
    __syncthreads();

    // fx on halo-1 extended tile, conv of |d1 - x1| (zero outside image)
    for (int i = tid; i < (TY+2)*(TX+2); i += NT) {
        int ly = i / (TX+2), lx = i % (TX+2);
        int gy = y0 + ly - 1, gx = x0 + lx - 1;
        float a0 = 0.f, a1 = 0.f, a2 = 0.f, a3 = 0.f;
        float a4 = 0.f, a5 = 0.f, a6 = 0.f, a7 = 0.f;
        if (gy >= 0 && gy < HH && gx >= 0 && gx < WW) {
            #pragma unroll
            for (int c = 0; c < CC; c++) {
                #pragma unroll
                for (int k = 0; k < 9; k++) {
                    int yy = ly + k/3, xx = lx + k%3;
                    float v = fabsf(s_d1[c][yy][xx] - s_x1[yy][xx]);
                    float4 wa = *(const float4*)&s_We2[c*72 + k*8];
                    float4 wb = *(const float4*)&s_We2[c*72 + k*8 + 4];
                    a0 = fmaf(v, wa.x, a0); a1 = fmaf(v, wa.y, a1);
                    a2 = fmaf(v, wa.z, a2); a3 = fmaf(v, wa.w, a3);
                    a4 = fmaf(v, wb.x, a4); a5 = fmaf(v, wb.y, a5);
                    a6 = fmaf(v, wb.z, a6); a7 = fmaf(v, wb.w, a7);
                }
            }
        }
        s_fx[0][ly][lx] = a0; s_fx[1][ly][lx] = a1;
        s_fx[2][ly][lx] = a2; s_fx[3][ly][lx] = a3;
        s_fx[4][ly][lx] = a4; s_fx[5][ly][lx] = a5;
        s_fx[6][ly][lx] = a6; s_fx[7][ly][lx] = a7;
    }
    __syncthreads();

    const int ty = tid / TX, tx = tid % TX;
    const int gy = y0 + ty, gx = x0 + tx;
    const float x1c = s_x1[ty+2][tx+2];
    float* dout = &g_d1[dst][0] + (size_t)b * CC * HH * WW;

    #pragma unroll
    for (int g = 0; g < CC; g++) {
        const float cf  = s_f [g][ty+1][tx+1];
        const float cfx = s_fx[g][ty+1][tx+1];
        float ws0 = 0.f, ws1 = 0.f;
        #pragma unroll
        for (int k = 0; k < 9; k++) {
            const int dy = k/3, dx = k%3;
            float pf  = s_f [g][ty+dy][tx+dx];
            float pfx = s_fx[g][ty+dy][tx+dx];
            float df = pf - cf, dfx = pfx - cfx;
            float kern = __expf(-0.5f * fmaf(df, df, dfx*dfx));
            float4 w = s_Wg4[g*9 + k];
            ws0 = fmaf(kern, fmaf(pf, w.x, pfx * w.y), ws0);
            ws1 = fmaf(kern, fmaf(pf, w.z, pfx * w.w), ws1);
        }
        // softmax over (ALPHA*ws0, ALPHA*ws1), blend pairs (d1, x1)
        float s = 1.f / (1.f + __expf(-2.0f * (ws1 - ws0)));
        float d1c = s_d1[g][ty+2][tx+2];
        dout[((size_t)g*HH + gy)*WW + gx] = d1c + s * (x1c - d1c);
    }
}

// ---------------------------------------------------------------------------
extern "C" void kernel_launch(void* const* d_in, const int* in_sizes, int n_in,
                              void* d_out, int out_size)
{
    const float* d1  = (const float*)d_in[0];
    const float* We  = (const float*)d_in[1];
    const float* Wp  = (const float*)d_in[2];
    const float* We2 = (const float*)d_in[3];
    const float* Wg  = (const float*)d_in[4];
    float* out = (float*)d_out;

    dim3 grid(WW/TX, HH/TY, BB);
    const int HW = HH * WW;
    const int WSZ = CC*CC*9;     // 576 per block for We/Wp/We2
    const int GSZ = CC*2*9*2;    // 288 per block for Wg

    // block 0 reads the external input d1
    k_stage_a<<<grid, NT>>>(d1, 0, We + 0*WSZ, Wp + 0*WSZ, out, 0);
    k_stage_b<<<grid, NT>>>(d1, 0, 0, out + 0*HW, We2 + 0*WSZ, Wg + 0*GSZ);

    k_stage_a<<<grid, NT>>>(nullptr, 0, We + 1*WSZ, Wp + 1*WSZ, out, 1);
    k_stage_b<<<grid, NT>>>(nullptr, 0, 1, out + 1*HW, We2 + 1*WSZ, Wg + 1*GSZ);

    k_stage_a<<<grid, NT>>>(nullptr, 1, We + 2*WSZ, Wp + 2*WSZ, out, 2);
    k_stage_b<<<grid, NT>>>(nullptr, 1, 0, out + 2*HW, We2 + 2*WSZ, Wg + 2*GSZ);

    k_stage_a<<<grid, NT>>>(nullptr, 0, We + 3*WSZ, Wp + 3*WSZ, out, 3);
}